// round 8
// baseline (speedup 1.0000x reference)
#include <cuda_runtime.h>
#include <cuda_bf16.h>
#include <math.h>
#include <float.h>
#include <stdint.h>

// Problem constants
#define T_LEN   4096
#define C_DIM   2048
#define HQ      16
#define HKV     4
#define HD      128
#define WIN     1024
#define NKV     (HKV * HD)     // 512

// fp32 scratch
__device__ float g_Q[T_LEN * HQ * HD];
__device__ float g_K[T_LEN * NKV];
__device__ float g_cos[T_LEN * 64];
__device__ float g_sin[T_LEN * 64];

// bf16 split operands
__device__ __nv_bfloat16 g_xh[T_LEN * C_DIM],  g_xl[T_LEN * C_DIM];
__device__ __nv_bfloat16 g_yh[T_LEN * C_DIM],  g_yl[T_LEN * C_DIM];
__device__ __nv_bfloat16 g_qsh[T_LEN * C_DIM], g_qsl[T_LEN * C_DIM];   // Q rope+scaled split
__device__ __nv_bfloat16 g_ksh[T_LEN * NKV],   g_ksl[T_LEN * NKV];     // K rope split
__device__ __nv_bfloat16 g_vsh[T_LEN * NKV],   g_vsl[T_LEN * NKV];     // V split (from GEMM)
__device__ __nv_bfloat16 g_wqt_h[C_DIM * C_DIM], g_wqt_l[C_DIM * C_DIM];
__device__ __nv_bfloat16 g_wkt_h[NKV * C_DIM],   g_wkt_l[NKV * C_DIM];
__device__ __nv_bfloat16 g_wvt_h[NKV * C_DIM],   g_wvt_l[NKV * C_DIM];
__device__ __nv_bfloat16 g_wot_h[C_DIM * C_DIM], g_wot_l[C_DIM * C_DIM];

// ---------------------------------------------------------------------------
// helpers
// ---------------------------------------------------------------------------
__device__ __forceinline__ uint32_t smem_u32(const void* p) {
    return (uint32_t)__cvta_generic_to_shared(p);
}

__device__ __forceinline__ void split2(float a, float b, uint32_t& hi, uint32_t& lo) {
    __nv_bfloat16 ah = __float2bfloat16_rn(a);
    __nv_bfloat16 bh = __float2bfloat16_rn(b);
    __nv_bfloat162 h(ah, bh);
    hi = *(uint32_t*)&h;
    __nv_bfloat162 l(__float2bfloat16_rn(a - __bfloat162float(ah)),
                     __float2bfloat16_rn(b - __bfloat162float(bh)));
    lo = *(uint32_t*)&l;
}

#define LDMATRIX_X4(R0,R1,R2,R3,ADDR) \
    asm volatile("ldmatrix.sync.aligned.m8n8.x4.shared.b16 {%0,%1,%2,%3}, [%4];" \
        : "=r"(R0), "=r"(R1), "=r"(R2), "=r"(R3) : "r"(ADDR))

#define LDMATRIX_X4_T(R0,R1,R2,R3,ADDR) \
    asm volatile("ldmatrix.sync.aligned.m8n8.x4.trans.shared.b16 {%0,%1,%2,%3}, [%4];" \
        : "=r"(R0), "=r"(R1), "=r"(R2), "=r"(R3) : "r"(ADDR))

#define MMA_BF16(D, A0,A1,A2,A3, B0,B1) \
    asm volatile("mma.sync.aligned.m16n8k16.row.col.f32.bf16.bf16.f32 " \
        "{%0,%1,%2,%3}, {%4,%5,%6,%7}, {%8,%9}, {%0,%1,%2,%3};" \
        : "+f"((D)[0]), "+f"((D)[1]), "+f"((D)[2]), "+f"((D)[3]) \
        : "r"(A0), "r"(A1), "r"(A2), "r"(A3), "r"(B0), "r"(B1))

__device__ __forceinline__ void cp_async16(uint32_t dst, const void* src) {
    asm volatile("cp.async.cg.shared.global [%0], [%1], 16;" :: "r"(dst), "l"(src));
}
__device__ __forceinline__ void cp_commit() {
    asm volatile("cp.async.commit_group;" ::: "memory");
}
template <int NN> __device__ __forceinline__ void cp_wait() {
    asm volatile("cp.async.wait_group %0;" :: "n"(NN) : "memory");
}

// ---------------------------------------------------------------------------
// Prep kernels
// ---------------------------------------------------------------------------
__global__ void split_f32_kernel(const float* __restrict__ src,
                                 __nv_bfloat16* __restrict__ hi,
                                 __nv_bfloat16* __restrict__ lo, int n4)
{
    int i = blockIdx.x * blockDim.x + threadIdx.x;
    if (i >= n4) return;
    float4 v = ((const float4*)src)[i];
    uint32_t h0, l0, h1, l1;
    split2(v.x, v.y, h0, l0);
    split2(v.z, v.w, h1, l1);
    ((uint2*)hi)[i] = make_uint2(h0, h1);
    ((uint2*)lo)[i] = make_uint2(l0, l1);
}

__device__ __forceinline__ void transpose_split_body(
    const float* __restrict__ W, __nv_bfloat16* __restrict__ Th,
    __nv_bfloat16* __restrict__ Tl, int Kd, int Nd)
{
    __shared__ float tile[32][33];
    const int bx = blockIdx.x;
    const int by = blockIdx.y;
    const int x = threadIdx.x;
    const int y = threadIdx.y;
#pragma unroll
    for (int j = 0; j < 32; j += 8)
        tile[y + j][x] = W[(size_t)(by * 32 + y + j) * Nd + bx * 32 + x];
    __syncthreads();
#pragma unroll
    for (int j = 0; j < 32; j += 8) {
        float v = tile[x][y + j];
        __nv_bfloat16 h = __float2bfloat16_rn(v);
        size_t o = (size_t)(bx * 32 + y + j) * Kd + by * 32 + x;
        Th[o] = h;
        Tl[o] = __float2bfloat16_rn(v - __bfloat162float(h));
    }
}

__global__ void transpose_qo_kernel(const float* __restrict__ Wq, const float* __restrict__ Wo)
{
    if (blockIdx.z == 0) transpose_split_body(Wq, g_wqt_h, g_wqt_l, C_DIM, C_DIM);
    else                 transpose_split_body(Wo, g_wot_h, g_wot_l, C_DIM, C_DIM);
}

__global__ void transpose_kv_kernel(const float* __restrict__ Wk, const float* __restrict__ Wv)
{
    if (blockIdx.z == 0) transpose_split_body(Wk, g_wkt_h, g_wkt_l, C_DIM, NKV);
    else                 transpose_split_body(Wv, g_wvt_h, g_wvt_l, C_DIM, NKV);
}

// ---------------------------------------------------------------------------
// bf16x3 GEMM on pre-split operands. 128x128 block, BK=64, 4 warps (64x64),
// 3-stage cp.async pipeline. Optional split-bf16 output epilogue.
// ---------------------------------------------------------------------------
#define G_AH 0
#define G_AL 16384
#define G_BH 32768
#define G_BL 49152
#define G_STAGE 65536
#define G_SMEM  (3 * G_STAGE)

__device__ __forceinline__ void g_load_stage(uint32_t dstbase,
    const __nv_bfloat16* __restrict__ Ah, const __nv_bfloat16* __restrict__ Al,
    const __nv_bfloat16* __restrict__ Bh, const __nv_bfloat16* __restrict__ Bl,
    int bm, int bn, int k0, int K, int tid)
{
    const int row = tid >> 3;
    const int c   = tid & 7;
    const uint32_t swc = (uint32_t)((c ^ (row & 7)) << 4);
#pragma unroll
    for (int jj = 0; jj < 8; jj++) {
        int r = row + 16 * jj;
        uint32_t so = (uint32_t)r * 128 + swc;
        size_t ga = (size_t)(bm + r) * K + k0 + c * 8;
        size_t gb = (size_t)(bn + r) * K + k0 + c * 8;
        cp_async16(dstbase + G_AH + so, Ah + ga);
        cp_async16(dstbase + G_AL + so, Al + ga);
        cp_async16(dstbase + G_BH + so, Bh + gb);
        cp_async16(dstbase + G_BL + so, Bl + gb);
    }
}

__device__ void gemm_body(
    const __nv_bfloat16* __restrict__ Ah, const __nv_bfloat16* __restrict__ Al,
    const __nv_bfloat16* __restrict__ Bh, const __nv_bfloat16* __restrict__ Bl,
    float* __restrict__ C, __nv_bfloat16* __restrict__ Ch, __nv_bfloat16* __restrict__ Cl,
    int splitout, int M, int N, int K, int bxx, int byy)
{
    extern __shared__ char smg[];
    const int tid  = threadIdx.x;
    const int wid  = tid >> 5;
    const int lane = tid & 31;
    const int warp_m = wid & 1;
    const int warp_n = wid >> 1;
    const int bm = byy * 128;
    const int bn = bxx * 128;
    const uint32_t sbase = smem_u32(smg);

    const int ar  = (lane & 7) | (((lane >> 3) & 1) << 3);
    const int ag  = lane >> 4;
    const int ar7 = ar & 7;
    const int br  = (lane & 7) | ((lane >> 4) << 3);
    const int bg  = (lane >> 3) & 1;
    const int br7 = lane & 7;

    uint32_t a_ro[4], b_ro[4];
#pragma unroll
    for (int mi = 0; mi < 4; mi++)
        a_ro[mi] = (uint32_t)(warp_m * 64 + mi * 16 + ar) * 128 + G_AH;
#pragma unroll
    for (int ng = 0; ng < 4; ng++)
        b_ro[ng] = (uint32_t)(warp_n * 64 + ng * 16 + br) * 128 + G_BH;

    float acc[4][8][4];
#pragma unroll
    for (int mi = 0; mi < 4; mi++)
#pragma unroll
        for (int nf = 0; nf < 8; nf++)
#pragma unroll
            for (int e = 0; e < 4; e++) acc[mi][nf][e] = 0.0f;

    const int NK = K >> 6;

    g_load_stage(sbase, Ah, Al, Bh, Bl, bm, bn, 0, K, tid);
    cp_commit();
    g_load_stage(sbase + G_STAGE, Ah, Al, Bh, Bl, bm, bn, 64, K, tid);
    cp_commit();

    int sidx = 0, lidx = 2;
    for (int i = 0; i < NK; i++) {
        cp_wait<1>();
        __syncthreads();

        if (i + 2 < NK)
            g_load_stage(sbase + lidx * G_STAGE, Ah, Al, Bh, Bl, bm, bn, (i + 2) * 64, K, tid);
        cp_commit();
        lidx = (lidx == 2) ? 0 : lidx + 1;

        const uint32_t stb = sbase + sidx * G_STAGE;
        sidx = (sidx == 2) ? 0 : sidx + 1;

#pragma unroll
        for (int ks = 0; ks < 4; ks++) {
            const uint32_t cA = (uint32_t)(((ks * 2 + ag) ^ ar7) << 4);
            const uint32_t cB = (uint32_t)(((ks * 2 + bg) ^ br7) << 4);
            uint32_t ahi[4][4], alo[4][4];
#pragma unroll
            for (int mi = 0; mi < 4; mi++) {
                uint32_t ad = stb + a_ro[mi] + cA;
                LDMATRIX_X4(ahi[mi][0], ahi[mi][1], ahi[mi][2], ahi[mi][3], ad);
                LDMATRIX_X4(alo[mi][0], alo[mi][1], alo[mi][2], alo[mi][3], ad + 16384);
            }
            uint32_t bhi[4][4], blo[4][4];
#pragma unroll
            for (int ng = 0; ng < 4; ng++) {
                uint32_t bd = stb + b_ro[ng] + cB;
                LDMATRIX_X4(bhi[ng][0], bhi[ng][1], bhi[ng][2], bhi[ng][3], bd);
                LDMATRIX_X4(blo[ng][0], blo[ng][1], blo[ng][2], blo[ng][3], bd + 16384);
            }
#pragma unroll
            for (int mi = 0; mi < 4; mi++)
#pragma unroll
                for (int ng = 0; ng < 4; ng++) {
                    MMA_BF16(acc[mi][2*ng],   ahi[mi][0], ahi[mi][1], ahi[mi][2], ahi[mi][3], bhi[ng][0], bhi[ng][1]);
                    MMA_BF16(acc[mi][2*ng+1], ahi[mi][0], ahi[mi][1], ahi[mi][2], ahi[mi][3], bhi[ng][2], bhi[ng][3]);
                }
#pragma unroll
            for (int mi = 0; mi < 4; mi++)
#pragma unroll
                for (int ng = 0; ng < 4; ng++) {
                    MMA_BF16(acc[mi][2*ng],   ahi[mi][0], ahi[mi][1], ahi[mi][2], ahi[mi][3], blo[ng][0], blo[ng][1]);
                    MMA_BF16(acc[mi][2*ng+1], ahi[mi][0], ahi[mi][1], ahi[mi][2], ahi[mi][3], blo[ng][2], blo[ng][3]);
                }
#pragma unroll
            for (int mi = 0; mi < 4; mi++)
#pragma unroll
                for (int ng = 0; ng < 4; ng++) {
                    MMA_BF16(acc[mi][2*ng],   alo[mi][0], alo[mi][1], alo[mi][2], alo[mi][3], bhi[ng][0], bhi[ng][1]);
                    MMA_BF16(acc[mi][2*ng+1], alo[mi][0], alo[mi][1], alo[mi][2], alo[mi][3], bhi[ng][2], bhi[ng][3]);
                }
        }
    }

    const int trow = lane >> 2;
    const int tcol = (lane & 3) << 1;
#pragma unroll
    for (int mi = 0; mi < 4; mi++) {
#pragma unroll
        for (int nf = 0; nf < 8; nf++) {
            int rg = bm + warp_m * 64 + mi * 16 + trow;
            int cg = bn + warp_n * 64 + nf * 8 + tcol;
            if (!splitout) {
                *(float2*)&C[(size_t)rg * N + cg]       = make_float2(acc[mi][nf][0], acc[mi][nf][1]);
                *(float2*)&C[(size_t)(rg + 8) * N + cg] = make_float2(acc[mi][nf][2], acc[mi][nf][3]);
            } else {
                uint32_t hh, ll;
                split2(acc[mi][nf][0], acc[mi][nf][1], hh, ll);
                *(uint32_t*)&Ch[(size_t)rg * N + cg] = hh;
                *(uint32_t*)&Cl[(size_t)rg * N + cg] = ll;
                split2(acc[mi][nf][2], acc[mi][nf][3], hh, ll);
                *(uint32_t*)&Ch[(size_t)(rg + 8) * N + cg] = hh;
                *(uint32_t*)&Cl[(size_t)(rg + 8) * N + cg] = ll;
            }
        }
    }
}

__global__ __launch_bounds__(128)
void gemm_one(const __nv_bfloat16* Ah, const __nv_bfloat16* Al,
              const __nv_bfloat16* Bh, const __nv_bfloat16* Bl,
              float* C, int M, int N, int K)
{
    gemm_body(Ah, Al, Bh, Bl, C, nullptr, nullptr, 0, M, N, K, blockIdx.x, blockIdx.y);
}

// z=0: K projection (fp32 out). z=1: V projection (split bf16 out).
__global__ __launch_bounds__(128)
void gemm_kv(const __nv_bfloat16* Ah, const __nv_bfloat16* Al, float* Kout)
{
    if (blockIdx.z == 0)
        gemm_body(Ah, Al, g_wkt_h, g_wkt_l, Kout, nullptr, nullptr, 0,
                  T_LEN, NKV, C_DIM, blockIdx.x, blockIdx.y);
    else
        gemm_body(Ah, Al, g_wvt_h, g_wvt_l, nullptr, g_vsh, g_vsl, 1,
                  T_LEN, NKV, C_DIM, blockIdx.x, blockIdx.y);
}

// ---------------------------------------------------------------------------
// RoPE
// ---------------------------------------------------------------------------
__global__ void rope_table_kernel()
{
    int idx = blockIdx.x * blockDim.x + threadIdx.x;
    if (idx >= T_LEN * 64) return;
    int t = idx >> 6;
    int j = idx & 63;
    double e = exp(-(double)j * (log(10000.0) / 64.0));
    float invf = (float)e;
    float ang = (float)t * invf;
    double a = (double)ang;
    g_cos[idx] = (float)cos(a);
    g_sin[idx] = (float)sin(a);
}

// Apply RoPE; write split bf16. Q additionally scaled by 1/sqrt(128)*log2(e).
__global__ void rope_apply_split_kernel(const float* __restrict__ Q,
                                        const float* __restrict__ K)
{
    const float SCQ = (float)(0.08838834764831845 * 1.4426950408889634);
    const int NQ = T_LEN * HQ * 64;
    int idx = blockIdx.x * blockDim.x + threadIdx.x;
    int t, j;
    if (idx < NQ) {
        t = idx >> 10;
        int rem = idx & 1023;
        int h = rem >> 6;
        j = rem & 63;
        const float* p = Q + (size_t)t * C_DIM + h * HD;
        float cv = g_cos[t * 64 + j];
        float sv = g_sin[t * 64 + j];
        float x0 = p[j];
        float x1 = p[j + 64];
        float r0 = (x0 * cv - x1 * sv) * SCQ;
        float r1 = (x1 * cv + x0 * sv) * SCQ;
        size_t o = (size_t)t * C_DIM + h * HD;
        __nv_bfloat16 h0 = __float2bfloat16_rn(r0);
        __nv_bfloat16 h1 = __float2bfloat16_rn(r1);
        g_qsh[o + j]      = h0;
        g_qsh[o + j + 64] = h1;
        g_qsl[o + j]      = __float2bfloat16_rn(r0 - __bfloat162float(h0));
        g_qsl[o + j + 64] = __float2bfloat16_rn(r1 - __bfloat162float(h1));
    } else {
        int i2 = idx - NQ;
        t = i2 >> 8;
        int rem = i2 & 255;
        int h = rem >> 6;
        j = rem & 63;
        const float* p = K + (size_t)t * NKV + h * HD;
        float cv = g_cos[t * 64 + j];
        float sv = g_sin[t * 64 + j];
        float x0 = p[j];
        float x1 = p[j + 64];
        float r0 = x0 * cv - x1 * sv;
        float r1 = x1 * cv + x0 * sv;
        size_t o = (size_t)t * NKV + h * HD;
        __nv_bfloat16 h0 = __float2bfloat16_rn(r0);
        __nv_bfloat16 h1 = __float2bfloat16_rn(r1);
        g_ksh[o + j]      = h0;
        g_ksh[o + j + 64] = h1;
        g_ksl[o + j]      = __float2bfloat16_rn(r0 - __bfloat162float(h0));
        g_ksl[o + j + 64] = __float2bfloat16_rn(r1 - __bfloat162float(h1));
    }
}

// ---------------------------------------------------------------------------
// Tensor-core flash attention on pre-split bf16 operands.
// Grid: (T/64, HQ). Block: 128 threads. K/V tiles via cp.async double buffer.
// ---------------------------------------------------------------------------
#define KVS   136                       // bf16 elems per smem row (272B)
#define AR_SZ (32 * KVS * 2)            // 8704 B per array
#define A_KH  0
#define A_KL  AR_SZ
#define A_VH  (2 * AR_SZ)
#define A_VL  (3 * AR_SZ)
#define ATT_STAGE (4 * AR_SZ)           // 34816
#define ATT_SMEM  (2 * ATT_STAGE)       // 69632

__device__ __forceinline__ void attn_load_kv(uint32_t dstbase, int jb, int kvh, int tid)
{
#pragma unroll
    for (int i = 0; i < 4; i++) {
        int idx = tid + 128 * i;          // 0..511
        int row = idx >> 4;
        int c16 = idx & 15;               // 16B granule within 256B of data
        uint32_t so = (uint32_t)row * (KVS * 2) + c16 * 16;
        size_t g = (size_t)(jb + row) * NKV + kvh * HD + c16 * 8;
        cp_async16(dstbase + A_KH + so, g_ksh + g);
        cp_async16(dstbase + A_KL + so, g_ksl + g);
        cp_async16(dstbase + A_VH + so, g_vsh + g);
        cp_async16(dstbase + A_VL + so, g_vsl + g);
    }
}

__global__ __launch_bounds__(128)
void attn_tc_kernel(__nv_bfloat16* __restrict__ Yh, __nv_bfloat16* __restrict__ Yl)
{
    extern __shared__ char sma[];
    const uint32_t sbase = smem_u32(sma);

    const int qb  = blockIdx.x;
    const int h   = blockIdx.y;
    const int kvh = h >> 2;
    const int tid  = threadIdx.x;
    const int wid  = tid >> 5;
    const int lane = tid & 31;
    const int trow = lane >> 2;
    const int tc2  = (lane & 3) << 1;
    const int qrow0 = qb * 64 + wid * 16;

    // Q fragments from pre-split (and pre-scaled) gmem
    uint32_t qhi[8][4], qlo[8][4];
#pragma unroll
    for (int ks = 0; ks < 8; ks++) {
#pragma unroll
        for (int r = 0; r < 4; r++) {
            int row = qrow0 + trow + ((r & 1) << 3);
            int d = ks * 16 + ((r >> 1) << 3) + tc2;
            size_t o = (size_t)row * C_DIM + h * HD + d;
            qhi[ks][r] = *(const uint32_t*)&g_qsh[o];
            qlo[ks][r] = *(const uint32_t*)&g_qsl[o];
        }
    }

    float oacc[16][4];
#pragma unroll
    for (int nf = 0; nf < 16; nf++)
#pragma unroll
        for (int e = 0; e < 4; e++) oacc[nf][e] = 0.0f;
    float m2[2]   = { -1e30f, -1e30f };
    float lsum[2] = { 0.0f, 0.0f };

    int jmin = qb * 64 - (WIN - 1);
    if (jmin < 0) jmin = 0;
    const int kb0 = jmin >> 5;
    const int kb1 = (qb * 64 + 63) >> 5;

    const int krow    = (lane & 7) + ((lane >> 4) << 3);
    const int kcoloff = ((lane >> 3) & 1) << 3;
    const int vrow    = (lane & 7) + (((lane >> 3) & 1) << 3);
    const int vcoloff = (lane >> 4) << 3;

    const uint32_t kh_ro = (uint32_t)(krow * KVS + kcoloff) * 2;
    const uint32_t vh_ro = (uint32_t)(vrow * KVS + vcoloff) * 2;
    const uint32_t KROW16 = (uint32_t)(16 * KVS) * 2;

    attn_load_kv(sbase, kb0 * 32, kvh, tid);
    cp_commit();

    int s = 0;
    for (int kb = kb0; kb <= kb1; kb++) {
        const int jb = kb * 32;
        if (kb < kb1) {
            attn_load_kv(sbase + (s ^ 1) * ATT_STAGE, (kb + 1) * 32, kvh, tid);
            cp_commit();
            cp_wait<1>();
        } else {
            cp_wait<0>();
        }
        __syncthreads();

        const uint32_t stb = sbase + s * ATT_STAGE;
        const uint32_t kh_base = stb + A_KH + kh_ro;
        const uint32_t kl_base = stb + A_KL + kh_ro;
        const uint32_t vh_base = stb + A_VH + vh_ro;
        const uint32_t vl_base = stb + A_VL + vh_ro;

        float sacc[4][4];
#pragma unroll
        for (int f = 0; f < 4; f++)
#pragma unroll
            for (int e = 0; e < 4; e++) sacc[f][e] = 0.0f;

#pragma unroll
        for (int ks = 0; ks < 8; ks++) {
            uint32_t off = (uint32_t)(ks * 16) * 2;
            uint32_t bh0[4], bh1[4], bl0[4], bl1[4];
            LDMATRIX_X4(bh0[0], bh0[1], bh0[2], bh0[3], kh_base + off);
            LDMATRIX_X4(bh1[0], bh1[1], bh1[2], bh1[3], kh_base + off + KROW16);
            LDMATRIX_X4(bl0[0], bl0[1], bl0[2], bl0[3], kl_base + off);
            LDMATRIX_X4(bl1[0], bl1[1], bl1[2], bl1[3], kl_base + off + KROW16);
            MMA_BF16(sacc[0], qhi[ks][0], qhi[ks][1], qhi[ks][2], qhi[ks][3], bh0[0], bh0[1]);
            MMA_BF16(sacc[1], qhi[ks][0], qhi[ks][1], qhi[ks][2], qhi[ks][3], bh0[2], bh0[3]);
            MMA_BF16(sacc[2], qhi[ks][0], qhi[ks][1], qhi[ks][2], qhi[ks][3], bh1[0], bh1[1]);
            MMA_BF16(sacc[3], qhi[ks][0], qhi[ks][1], qhi[ks][2], qhi[ks][3], bh1[2], bh1[3]);
            MMA_BF16(sacc[0], qlo[ks][0], qlo[ks][1], qlo[ks][2], qlo[ks][3], bh0[0], bh0[1]);
            MMA_BF16(sacc[1], qlo[ks][0], qlo[ks][1], qlo[ks][2], qlo[ks][3], bh0[2], bh0[3]);
            MMA_BF16(sacc[2], qlo[ks][0], qlo[ks][1], qlo[ks][2], qlo[ks][3], bh1[0], bh1[1]);
            MMA_BF16(sacc[3], qlo[ks][0], qlo[ks][1], qlo[ks][2], qlo[ks][3], bh1[2], bh1[3]);
            MMA_BF16(sacc[0], qhi[ks][0], qhi[ks][1], qhi[ks][2], qhi[ks][3], bl0[0], bl0[1]);
            MMA_BF16(sacc[1], qhi[ks][0], qhi[ks][1], qhi[ks][2], qhi[ks][3], bl0[2], bl0[3]);
            MMA_BF16(sacc[2], qhi[ks][0], qhi[ks][1], qhi[ks][2], qhi[ks][3], bl1[0], bl1[1]);
            MMA_BF16(sacc[3], qhi[ks][0], qhi[ks][1], qhi[ks][2], qhi[ks][3], bl1[2], bl1[3]);
        }

        // masked online softmax (Q pre-scaled: no multiply here)
        float bm0 = -1e30f, bm1 = -1e30f;
#pragma unroll
        for (int f = 0; f < 4; f++) {
            int j0 = jb + f * 8 + tc2;
#pragma unroll
            for (int e = 0; e < 4; e++) {
                int j  = j0 + (e & 1);
                int qi = qrow0 + trow + ((e >> 1) << 3);
                bool ok = (j <= qi) && ((qi - j) < WIN);
                float sx = ok ? sacc[f][e] : -1e30f;
                sacc[f][e] = sx;
                if (e < 2) bm0 = fmaxf(bm0, sx); else bm1 = fmaxf(bm1, sx);
            }
        }
        bm0 = fmaxf(bm0, __shfl_xor_sync(0xffffffffu, bm0, 1));
        bm0 = fmaxf(bm0, __shfl_xor_sync(0xffffffffu, bm0, 2));
        bm1 = fmaxf(bm1, __shfl_xor_sync(0xffffffffu, bm1, 1));
        bm1 = fmaxf(bm1, __shfl_xor_sync(0xffffffffu, bm1, 2));

        float mn0 = fmaxf(m2[0], bm0);
        float mn1 = fmaxf(m2[1], bm1);
        float mm0 = fmaxf(mn0, -1e20f);
        float mm1 = fmaxf(mn1, -1e20f);
        float f0 = exp2f(m2[0] - mm0);
        float f1 = exp2f(m2[1] - mm1);
        m2[0] = mn0; m2[1] = mn1;

        float ps0 = 0.0f, ps1 = 0.0f;
#pragma unroll
        for (int f = 0; f < 4; f++) {
            sacc[f][0] = exp2f(sacc[f][0] - mm0);
            sacc[f][1] = exp2f(sacc[f][1] - mm0);
            sacc[f][2] = exp2f(sacc[f][2] - mm1);
            sacc[f][3] = exp2f(sacc[f][3] - mm1);
            ps0 += sacc[f][0] + sacc[f][1];
            ps1 += sacc[f][2] + sacc[f][3];
        }
        ps0 += __shfl_xor_sync(0xffffffffu, ps0, 1);
        ps0 += __shfl_xor_sync(0xffffffffu, ps0, 2);
        ps1 += __shfl_xor_sync(0xffffffffu, ps1, 1);
        ps1 += __shfl_xor_sync(0xffffffffu, ps1, 2);
        lsum[0] = lsum[0] * f0 + ps0;
        lsum[1] = lsum[1] * f1 + ps1;

#pragma unroll
        for (int nf = 0; nf < 16; nf++) {
            oacc[nf][0] *= f0; oacc[nf][1] *= f0;
            oacc[nf][2] *= f1; oacc[nf][3] *= f1;
        }

        uint32_t phi[2][4], plo[2][4];
#pragma unroll
        for (int kp = 0; kp < 2; kp++) {
            split2(sacc[2*kp][0],   sacc[2*kp][1],   phi[kp][0], plo[kp][0]);
            split2(sacc[2*kp][2],   sacc[2*kp][3],   phi[kp][1], plo[kp][1]);
            split2(sacc[2*kp+1][0], sacc[2*kp+1][1], phi[kp][2], plo[kp][2]);
            split2(sacc[2*kp+1][2], sacc[2*kp+1][3], phi[kp][3], plo[kp][3]);
        }

#pragma unroll
        for (int kp = 0; kp < 2; kp++) {
            uint32_t rowoff = (uint32_t)(kp * 16 * KVS) * 2;
#pragma unroll
            for (int ng = 0; ng < 8; ng++) {
                uint32_t coff = rowoff + (uint32_t)(ng * 16) * 2;
                uint32_t vh4[4], vl4[4];
                LDMATRIX_X4_T(vh4[0], vh4[1], vh4[2], vh4[3], vh_base + coff);
                LDMATRIX_X4_T(vl4[0], vl4[1], vl4[2], vl4[3], vl_base + coff);
                MMA_BF16(oacc[2*ng],   phi[kp][0], phi[kp][1], phi[kp][2], phi[kp][3], vh4[0], vh4[1]);
                MMA_BF16(oacc[2*ng+1], phi[kp][0], phi[kp][1], phi[kp][2], phi[kp][3], vh4[2], vh4[3]);
                MMA_BF16(oacc[2*ng],   plo[kp][0], plo[kp][1], plo[kp][2], plo[kp][3], vh4[0], vh4[1]);
                MMA_BF16(oacc[2*ng+1], plo[kp][0], plo[kp][1], plo[kp][2], plo[kp][3], vh4[2], vh4[3]);
                MMA_BF16(oacc[2*ng],   phi[kp][0], phi[kp][1], phi[kp][2], phi[kp][3], vl4[0], vl4[1]);
                MMA_BF16(oacc[2*ng+1], phi[kp][0], phi[kp][1], phi[kp][2], phi[kp][3], vl4[2], vl4[3]);
            }
        }
        __syncthreads();
        s ^= 1;
    }

    float il0 = 1.0f / lsum[0];
    float il1 = 1.0f / lsum[1];
    const int row0 = qrow0 + trow;
#pragma unroll
    for (int nf = 0; nf < 16; nf++) {
        int col = h * HD + nf * 8 + tc2;
        uint32_t hh, ll;
        split2(oacc[nf][0] * il0, oacc[nf][1] * il0, hh, ll);
        *(uint32_t*)&Yh[(size_t)row0 * C_DIM + col] = hh;
        *(uint32_t*)&Yl[(size_t)row0 * C_DIM + col] = ll;
        split2(oacc[nf][2] * il1, oacc[nf][3] * il1, hh, ll);
        *(uint32_t*)&Yh[(size_t)(row0 + 8) * C_DIM + col] = hh;
        *(uint32_t*)&Yl[(size_t)(row0 + 8) * C_DIM + col] = ll;
    }
}

// ---------------------------------------------------------------------------
// Launch (slot 6 = Wq GEMM for ncu capture)
// ---------------------------------------------------------------------------
extern "C" void kernel_launch(void* const* d_in, const int* in_sizes, int n_in,
                              void* d_out, int out_size)
{
    const float* x  = (const float*)d_in[0];
    const float* Wq = (const float*)d_in[1];
    const float* Wk = (const float*)d_in[2];
    const float* Wv = (const float*)d_in[3];
    const float* Wo = (const float*)d_in[4];
    float* out = (float*)d_out;

    float *Q, *Kp;
    cudaGetSymbolAddress((void**)&Q,  g_Q);
    cudaGetSymbolAddress((void**)&Kp, g_K);

    __nv_bfloat16 *xh, *xl, *yh, *yl, *wqh, *wql, *woh, *wol;
    cudaGetSymbolAddress((void**)&xh, g_xh);
    cudaGetSymbolAddress((void**)&xl, g_xl);
    cudaGetSymbolAddress((void**)&yh, g_yh);
    cudaGetSymbolAddress((void**)&yl, g_yl);
    cudaGetSymbolAddress((void**)&wqh, g_wqt_h);
    cudaGetSymbolAddress((void**)&wql, g_wqt_l);
    cudaGetSymbolAddress((void**)&woh, g_wot_h);
    cudaGetSymbolAddress((void**)&wol, g_wot_l);

    static bool attr_done = false;
    if (!attr_done) {
        cudaFuncSetAttribute(gemm_one, cudaFuncAttributeMaxDynamicSharedMemorySize, G_SMEM);
        cudaFuncSetAttribute(gemm_kv,  cudaFuncAttributeMaxDynamicSharedMemorySize, G_SMEM);
        cudaFuncSetAttribute(attn_tc_kernel, cudaFuncAttributeMaxDynamicSharedMemorySize, ATT_SMEM);
        attr_done = true;
    }

    // 1-4: prep
    rope_table_kernel<<<(T_LEN * 64 + 255) / 256, 256>>>();
    split_f32_kernel<<<(T_LEN * C_DIM / 4 + 255) / 256, 256>>>(x, xh, xl, T_LEN * C_DIM / 4);
    transpose_kv_kernel<<<dim3(NKV / 32, C_DIM / 32, 2), dim3(32, 8)>>>(Wk, Wv);
    transpose_qo_kernel<<<dim3(C_DIM / 32, C_DIM / 32, 2), dim3(32, 8)>>>(Wq, Wo);

    // 5: K+V projections (z-dispatch; V writes split bf16)
    gemm_kv<<<dim3(NKV / 128, T_LEN / 128, 2), 128, G_SMEM>>>(xh, xl, Kp);
    // 6: Q projection (ncu capture slot)
    gemm_one<<<dim3((HQ * HD) / 128, T_LEN / 128), 128, G_SMEM>>>(xh, xl, wqh, wql, Q, T_LEN, HQ * HD, C_DIM);

    // 7: RoPE + split (Q scaled)
    const int n_rope = T_LEN * HQ * 64 + T_LEN * HKV * 64;
    rope_apply_split_kernel<<<n_rope / 256, 256>>>(Q, Kp);

    // 8: attention
    attn_tc_kernel<<<dim3(T_LEN / 64, HQ), 128, ATT_SMEM>>>(yh, yl);

    // 9: output projection
    gemm_one<<<dim3(C_DIM / 128, T_LEN / 128), 128, G_SMEM>>>(yh, yl, woh, wol, out, T_LEN, C_DIM, C_DIM);
}

// round 9
// speedup vs baseline: 1.0989x; 1.0989x over previous
#include <cuda_runtime.h>
#include <cuda_bf16.h>
#include <math.h>
#include <float.h>
#include <stdint.h>

// Problem constants
#define T_LEN   4096
#define C_DIM   2048
#define HQ      16
#define HKV     4
#define HD      128
#define WIN     1024
#define NKV     (HKV * HD)     // 512

// fp32 scratch
__device__ float g_Q[T_LEN * HQ * HD];
__device__ float g_K[T_LEN * NKV];
__device__ float g_cos[T_LEN * 64];
__device__ float g_sin[T_LEN * 64];

// bf16 split operands
__device__ __nv_bfloat16 g_xh[T_LEN * C_DIM],  g_xl[T_LEN * C_DIM];
__device__ __nv_bfloat16 g_yh[T_LEN * C_DIM],  g_yl[T_LEN * C_DIM];
__device__ __nv_bfloat16 g_qsh[T_LEN * C_DIM], g_qsl[T_LEN * C_DIM];
__device__ __nv_bfloat16 g_ksh[T_LEN * NKV],   g_ksl[T_LEN * NKV];
__device__ __nv_bfloat16 g_vsh[T_LEN * NKV],   g_vsl[T_LEN * NKV];
__device__ __nv_bfloat16 g_wqt_h[C_DIM * C_DIM], g_wqt_l[C_DIM * C_DIM];
__device__ __nv_bfloat16 g_wkt_h[NKV * C_DIM],   g_wkt_l[NKV * C_DIM];
__device__ __nv_bfloat16 g_wvt_h[NKV * C_DIM],   g_wvt_l[NKV * C_DIM];
__device__ __nv_bfloat16 g_wot_h[C_DIM * C_DIM], g_wot_l[C_DIM * C_DIM];

// ---------------------------------------------------------------------------
// helpers
// ---------------------------------------------------------------------------
__device__ __forceinline__ uint32_t smem_u32(const void* p) {
    return (uint32_t)__cvta_generic_to_shared(p);
}

__device__ __forceinline__ void split2(float a, float b, uint32_t& hi, uint32_t& lo) {
    __nv_bfloat16 ah = __float2bfloat16_rn(a);
    __nv_bfloat16 bh = __float2bfloat16_rn(b);
    __nv_bfloat162 h(ah, bh);
    hi = *(uint32_t*)&h;
    __nv_bfloat162 l(__float2bfloat16_rn(a - __bfloat162float(ah)),
                     __float2bfloat16_rn(b - __bfloat162float(bh)));
    lo = *(uint32_t*)&l;
}

#define LDMATRIX_X4(R0,R1,R2,R3,ADDR) \
    asm volatile("ldmatrix.sync.aligned.m8n8.x4.shared.b16 {%0,%1,%2,%3}, [%4];" \
        : "=r"(R0), "=r"(R1), "=r"(R2), "=r"(R3) : "r"(ADDR))

#define LDMATRIX_X4_T(R0,R1,R2,R3,ADDR) \
    asm volatile("ldmatrix.sync.aligned.m8n8.x4.trans.shared.b16 {%0,%1,%2,%3}, [%4];" \
        : "=r"(R0), "=r"(R1), "=r"(R2), "=r"(R3) : "r"(ADDR))

#define MMA_BF16(D, A0,A1,A2,A3, B0,B1) \
    asm volatile("mma.sync.aligned.m16n8k16.row.col.f32.bf16.bf16.f32 " \
        "{%0,%1,%2,%3}, {%4,%5,%6,%7}, {%8,%9}, {%0,%1,%2,%3};" \
        : "+f"((D)[0]), "+f"((D)[1]), "+f"((D)[2]), "+f"((D)[3]) \
        : "r"(A0), "r"(A1), "r"(A2), "r"(A3), "r"(B0), "r"(B1))

__device__ __forceinline__ void cp_async16(uint32_t dst, const void* src) {
    asm volatile("cp.async.cg.shared.global [%0], [%1], 16;" :: "r"(dst), "l"(src));
}
__device__ __forceinline__ void cp_commit() {
    asm volatile("cp.async.commit_group;" ::: "memory");
}
template <int NN> __device__ __forceinline__ void cp_wait() {
    asm volatile("cp.async.wait_group %0;" :: "n"(NN) : "memory");
}

// ---------------------------------------------------------------------------
// Prep kernels
// ---------------------------------------------------------------------------
__global__ void split_f32_kernel(const float* __restrict__ src,
                                 __nv_bfloat16* __restrict__ hi,
                                 __nv_bfloat16* __restrict__ lo, int n4)
{
    int i = blockIdx.x * blockDim.x + threadIdx.x;
    if (i >= n4) return;
    float4 v = ((const float4*)src)[i];
    uint32_t h0, l0, h1, l1;
    split2(v.x, v.y, h0, l0);
    split2(v.z, v.w, h1, l1);
    ((uint2*)hi)[i] = make_uint2(h0, h1);
    ((uint2*)lo)[i] = make_uint2(l0, l1);
}

__device__ __forceinline__ void transpose_split_body(
    const float* __restrict__ W, __nv_bfloat16* __restrict__ Th,
    __nv_bfloat16* __restrict__ Tl, int Kd, int Nd)
{
    __shared__ float tile[32][33];
    const int bx = blockIdx.x;
    const int by = blockIdx.y;
    const int x = threadIdx.x;
    const int y = threadIdx.y;
#pragma unroll
    for (int j = 0; j < 32; j += 8)
        tile[y + j][x] = W[(size_t)(by * 32 + y + j) * Nd + bx * 32 + x];
    __syncthreads();
#pragma unroll
    for (int j = 0; j < 32; j += 8) {
        float v = tile[x][y + j];
        __nv_bfloat16 h = __float2bfloat16_rn(v);
        size_t o = (size_t)(bx * 32 + y + j) * Kd + by * 32 + x;
        Th[o] = h;
        Tl[o] = __float2bfloat16_rn(v - __bfloat162float(h));
    }
}

__global__ void transpose_qo_kernel(const float* __restrict__ Wq, const float* __restrict__ Wo)
{
    if (blockIdx.z == 0) transpose_split_body(Wq, g_wqt_h, g_wqt_l, C_DIM, C_DIM);
    else                 transpose_split_body(Wo, g_wot_h, g_wot_l, C_DIM, C_DIM);
}

__global__ void transpose_kv_kernel(const float* __restrict__ Wk, const float* __restrict__ Wv)
{
    if (blockIdx.z == 0) transpose_split_body(Wk, g_wkt_h, g_wkt_l, C_DIM, NKV);
    else                 transpose_split_body(Wv, g_wvt_h, g_wvt_l, C_DIM, NKV);
}

// ---------------------------------------------------------------------------
// bf16x3 GEMM: C[M,N] = A[M,K] * B[N,K]^T, pre-split bf16 operands.
// 256x128 block tile, BK=64, 256 threads (8 warps, 64x64 warp tiles),
// 2-stage cp.async pipeline (192KB smem). Optional split-bf16 output.
// ---------------------------------------------------------------------------
#define G2_AH 0
#define G2_AL 32768
#define G2_BH 65536
#define G2_BL 81920
#define G2_STAGE 98304
#define G2_SMEM  (2 * G2_STAGE)   // 196608

__device__ __forceinline__ void g_load_stage(uint32_t dstbase,
    const __nv_bfloat16* __restrict__ Ah, const __nv_bfloat16* __restrict__ Al,
    const __nv_bfloat16* __restrict__ Bh, const __nv_bfloat16* __restrict__ Bl,
    int bm, int bn, int k0, int K, int tid)
{
    const int row = tid >> 3;          // 0..31
    const int c   = tid & 7;
    const uint32_t swc = (uint32_t)((c ^ (row & 7)) << 4);
#pragma unroll
    for (int jj = 0; jj < 8; jj++) {   // A: 256 rows
        int r = row + 32 * jj;
        uint32_t so = (uint32_t)r * 128 + swc;
        size_t ga = (size_t)(bm + r) * K + k0 + c * 8;
        cp_async16(dstbase + G2_AH + so, Ah + ga);
        cp_async16(dstbase + G2_AL + so, Al + ga);
    }
#pragma unroll
    for (int jj = 0; jj < 4; jj++) {   // B: 128 rows
        int r = row + 32 * jj;
        uint32_t so = (uint32_t)r * 128 + swc;
        size_t gb = (size_t)(bn + r) * K + k0 + c * 8;
        cp_async16(dstbase + G2_BH + so, Bh + gb);
        cp_async16(dstbase + G2_BL + so, Bl + gb);
    }
}

__device__ void gemm_body(
    const __nv_bfloat16* __restrict__ Ah, const __nv_bfloat16* __restrict__ Al,
    const __nv_bfloat16* __restrict__ Bh, const __nv_bfloat16* __restrict__ Bl,
    float* __restrict__ C, __nv_bfloat16* __restrict__ Ch, __nv_bfloat16* __restrict__ Cl,
    int splitout, int M, int N, int K, int bxx, int byy)
{
    extern __shared__ char smg[];
    const int tid  = threadIdx.x;
    const int wid  = tid >> 5;
    const int lane = tid & 31;
    const int warp_m = wid & 3;        // 4 warps along M (64 rows each)
    const int warp_n = wid >> 2;       // 2 warps along N (64 cols each)
    const int bm = byy * 256;
    const int bn = bxx * 128;
    const uint32_t sbase = smem_u32(smg);

    const int ar  = (lane & 7) | (((lane >> 3) & 1) << 3);
    const int ag  = lane >> 4;
    const int ar7 = ar & 7;
    const int br  = (lane & 7) | ((lane >> 4) << 3);
    const int bg  = (lane >> 3) & 1;
    const int br7 = lane & 7;

    uint32_t a_ro[4], b_ro[4];
#pragma unroll
    for (int mi = 0; mi < 4; mi++)
        a_ro[mi] = (uint32_t)(warp_m * 64 + mi * 16 + ar) * 128 + G2_AH;
#pragma unroll
    for (int ng = 0; ng < 4; ng++)
        b_ro[ng] = (uint32_t)(warp_n * 64 + ng * 16 + br) * 128 + G2_BH;

    float acc[4][8][4];
#pragma unroll
    for (int mi = 0; mi < 4; mi++)
#pragma unroll
        for (int nf = 0; nf < 8; nf++)
#pragma unroll
            for (int e = 0; e < 4; e++) acc[mi][nf][e] = 0.0f;

    const int NK = K >> 6;

    g_load_stage(sbase, Ah, Al, Bh, Bl, bm, bn, 0, K, tid);
    cp_commit();

    for (int i = 0; i < NK; i++) {
        cp_wait<0>();          // only load(i) outstanding
        __syncthreads();       // data visible; previous compute done (stage free)

        if (i + 1 < NK) {
            g_load_stage(sbase + ((i + 1) & 1) * G2_STAGE, Ah, Al, Bh, Bl,
                         bm, bn, (i + 1) * 64, K, tid);
            cp_commit();
        }

        const uint32_t stb = sbase + (i & 1) * G2_STAGE;
#pragma unroll
        for (int ks = 0; ks < 4; ks++) {
            const uint32_t cA = (uint32_t)(((ks * 2 + ag) ^ ar7) << 4);
            const uint32_t cB = (uint32_t)(((ks * 2 + bg) ^ br7) << 4);
            uint32_t ahi[4][4], alo[4][4];
#pragma unroll
            for (int mi = 0; mi < 4; mi++) {
                uint32_t ad = stb + a_ro[mi] + cA;
                LDMATRIX_X4(ahi[mi][0], ahi[mi][1], ahi[mi][2], ahi[mi][3], ad);
                LDMATRIX_X4(alo[mi][0], alo[mi][1], alo[mi][2], alo[mi][3], ad + 32768);
            }
            uint32_t bhi[4][4], blo[4][4];
#pragma unroll
            for (int ng = 0; ng < 4; ng++) {
                uint32_t bd = stb + b_ro[ng] + cB;
                LDMATRIX_X4(bhi[ng][0], bhi[ng][1], bhi[ng][2], bhi[ng][3], bd);
                LDMATRIX_X4(blo[ng][0], blo[ng][1], blo[ng][2], blo[ng][3], bd + 16384);
            }
#pragma unroll
            for (int mi = 0; mi < 4; mi++)
#pragma unroll
                for (int ng = 0; ng < 4; ng++) {
                    MMA_BF16(acc[mi][2*ng],   ahi[mi][0], ahi[mi][1], ahi[mi][2], ahi[mi][3], bhi[ng][0], bhi[ng][1]);
                    MMA_BF16(acc[mi][2*ng+1], ahi[mi][0], ahi[mi][1], ahi[mi][2], ahi[mi][3], bhi[ng][2], bhi[ng][3]);
                }
#pragma unroll
            for (int mi = 0; mi < 4; mi++)
#pragma unroll
                for (int ng = 0; ng < 4; ng++) {
                    MMA_BF16(acc[mi][2*ng],   ahi[mi][0], ahi[mi][1], ahi[mi][2], ahi[mi][3], blo[ng][0], blo[ng][1]);
                    MMA_BF16(acc[mi][2*ng+1], ahi[mi][0], ahi[mi][1], ahi[mi][2], ahi[mi][3], blo[ng][2], blo[ng][3]);
                }
#pragma unroll
            for (int mi = 0; mi < 4; mi++)
#pragma unroll
                for (int ng = 0; ng < 4; ng++) {
                    MMA_BF16(acc[mi][2*ng],   alo[mi][0], alo[mi][1], alo[mi][2], alo[mi][3], bhi[ng][0], bhi[ng][1]);
                    MMA_BF16(acc[mi][2*ng+1], alo[mi][0], alo[mi][1], alo[mi][2], alo[mi][3], bhi[ng][2], bhi[ng][3]);
                }
        }
        __syncthreads();       // all warps done with stage before next overwrite
    }

    const int trow = lane >> 2;
    const int tcol = (lane & 3) << 1;
#pragma unroll
    for (int mi = 0; mi < 4; mi++) {
#pragma unroll
        for (int nf = 0; nf < 8; nf++) {
            int rg = bm + warp_m * 64 + mi * 16 + trow;
            int cg = bn + warp_n * 64 + nf * 8 + tcol;
            if (!splitout) {
                *(float2*)&C[(size_t)rg * N + cg]       = make_float2(acc[mi][nf][0], acc[mi][nf][1]);
                *(float2*)&C[(size_t)(rg + 8) * N + cg] = make_float2(acc[mi][nf][2], acc[mi][nf][3]);
            } else {
                uint32_t hh, ll;
                split2(acc[mi][nf][0], acc[mi][nf][1], hh, ll);
                *(uint32_t*)&Ch[(size_t)rg * N + cg] = hh;
                *(uint32_t*)&Cl[(size_t)rg * N + cg] = ll;
                split2(acc[mi][nf][2], acc[mi][nf][3], hh, ll);
                *(uint32_t*)&Ch[(size_t)(rg + 8) * N + cg] = hh;
                *(uint32_t*)&Cl[(size_t)(rg + 8) * N + cg] = ll;
            }
        }
    }
}

__global__ __launch_bounds__(256)
void gemm_one(const __nv_bfloat16* Ah, const __nv_bfloat16* Al,
              const __nv_bfloat16* Bh, const __nv_bfloat16* Bl,
              float* C, int M, int N, int K)
{
    gemm_body(Ah, Al, Bh, Bl, C, nullptr, nullptr, 0, M, N, K, blockIdx.x, blockIdx.y);
}

__global__ __launch_bounds__(256)
void gemm_kv(const __nv_bfloat16* Ah, const __nv_bfloat16* Al, float* Kout)
{
    if (blockIdx.z == 0)
        gemm_body(Ah, Al, g_wkt_h, g_wkt_l, Kout, nullptr, nullptr, 0,
                  T_LEN, NKV, C_DIM, blockIdx.x, blockIdx.y);
    else
        gemm_body(Ah, Al, g_wvt_h, g_wvt_l, nullptr, g_vsh, g_vsl, 1,
                  T_LEN, NKV, C_DIM, blockIdx.x, blockIdx.y);
}

// ---------------------------------------------------------------------------
// RoPE: fp64 exp for invf (bit-compat), fp32 sincosf on the fp32 angle.
// ---------------------------------------------------------------------------
__global__ void rope_table_kernel()
{
    __shared__ float s_invf[64];
    if (threadIdx.x < 64) {
        double e = exp(-(double)threadIdx.x * (log(10000.0) / 64.0));
        s_invf[threadIdx.x] = (float)e;
    }
    __syncthreads();
    int idx = blockIdx.x * blockDim.x + threadIdx.x;
    if (idx >= T_LEN * 64) return;
    int t = idx >> 6;
    int j = idx & 63;
    float ang = (float)t * s_invf[j];
    float s, c;
    sincosf(ang, &s, &c);
    g_cos[idx] = c;
    g_sin[idx] = s;
}

// RoPE apply + split, 2 j-values per thread. Q scaled by 1/sqrt(128)*log2(e).
__global__ void rope_apply_split_kernel(const float* __restrict__ Q,
                                        const float* __restrict__ K)
{
    const float SCQ = (float)(0.08838834764831845 * 1.4426950408889634);
    const int NQ2 = T_LEN * HQ * 32;
    int idx = blockIdx.x * blockDim.x + threadIdx.x;
    if (idx < NQ2) {
        int t = idx >> 9;
        int rem = idx & 511;
        int h = rem >> 5;
        int j2 = (rem & 31) << 1;
        size_t o = (size_t)t * C_DIM + h * HD;
        const float* p = Q + o;
        float2 x0 = *(const float2*)(p + j2);
        float2 x1 = *(const float2*)(p + j2 + 64);
        float2 cv = *(const float2*)(g_cos + t * 64 + j2);
        float2 sv = *(const float2*)(g_sin + t * 64 + j2);
        float r0a = (x0.x * cv.x - x1.x * sv.x) * SCQ;
        float r0b = (x0.y * cv.y - x1.y * sv.y) * SCQ;
        float r1a = (x1.x * cv.x + x0.x * sv.x) * SCQ;
        float r1b = (x1.y * cv.y + x0.y * sv.y) * SCQ;
        uint32_t hh, ll;
        split2(r0a, r0b, hh, ll);
        *(uint32_t*)&g_qsh[o + j2] = hh;
        *(uint32_t*)&g_qsl[o + j2] = ll;
        split2(r1a, r1b, hh, ll);
        *(uint32_t*)&g_qsh[o + j2 + 64] = hh;
        *(uint32_t*)&g_qsl[o + j2 + 64] = ll;
    } else {
        int i2 = idx - NQ2;
        int t = i2 >> 7;
        int rem = i2 & 127;
        int h = rem >> 5;
        int j2 = (rem & 31) << 1;
        size_t o = (size_t)t * NKV + h * HD;
        const float* p = K + o;
        float2 x0 = *(const float2*)(p + j2);
        float2 x1 = *(const float2*)(p + j2 + 64);
        float2 cv = *(const float2*)(g_cos + t * 64 + j2);
        float2 sv = *(const float2*)(g_sin + t * 64 + j2);
        float r0a = x0.x * cv.x - x1.x * sv.x;
        float r0b = x0.y * cv.y - x1.y * sv.y;
        float r1a = x1.x * cv.x + x0.x * sv.x;
        float r1b = x1.y * cv.y + x0.y * sv.y;
        uint32_t hh, ll;
        split2(r0a, r0b, hh, ll);
        *(uint32_t*)&g_ksh[o + j2] = hh;
        *(uint32_t*)&g_ksl[o + j2] = ll;
        split2(r1a, r1b, hh, ll);
        *(uint32_t*)&g_ksh[o + j2 + 64] = hh;
        *(uint32_t*)&g_ksl[o + j2 + 64] = ll;
    }
}

// ---------------------------------------------------------------------------
// Tensor-core flash attention on pre-split bf16 operands (unchanged).
// ---------------------------------------------------------------------------
#define KVS   136
#define AR_SZ (32 * KVS * 2)
#define A_KH  0
#define A_KL  AR_SZ
#define A_VH  (2 * AR_SZ)
#define A_VL  (3 * AR_SZ)
#define ATT_STAGE (4 * AR_SZ)
#define ATT_SMEM  (2 * ATT_STAGE)

__device__ __forceinline__ void attn_load_kv(uint32_t dstbase, int jb, int kvh, int tid)
{
#pragma unroll
    for (int i = 0; i < 4; i++) {
        int idx = tid + 128 * i;
        int row = idx >> 4;
        int c16 = idx & 15;
        uint32_t so = (uint32_t)row * (KVS * 2) + c16 * 16;
        size_t g = (size_t)(jb + row) * NKV + kvh * HD + c16 * 8;
        cp_async16(dstbase + A_KH + so, g_ksh + g);
        cp_async16(dstbase + A_KL + so, g_ksl + g);
        cp_async16(dstbase + A_VH + so, g_vsh + g);
        cp_async16(dstbase + A_VL + so, g_vsl + g);
    }
}

__global__ __launch_bounds__(128)
void attn_tc_kernel(__nv_bfloat16* __restrict__ Yh, __nv_bfloat16* __restrict__ Yl)
{
    extern __shared__ char sma[];
    const uint32_t sbase = smem_u32(sma);

    const int qb  = blockIdx.x;
    const int h   = blockIdx.y;
    const int kvh = h >> 2;
    const int tid  = threadIdx.x;
    const int wid  = tid >> 5;
    const int lane = tid & 31;
    const int trow = lane >> 2;
    const int tc2  = (lane & 3) << 1;
    const int qrow0 = qb * 64 + wid * 16;

    uint32_t qhi[8][4], qlo[8][4];
#pragma unroll
    for (int ks = 0; ks < 8; ks++) {
#pragma unroll
        for (int r = 0; r < 4; r++) {
            int row = qrow0 + trow + ((r & 1) << 3);
            int d = ks * 16 + ((r >> 1) << 3) + tc2;
            size_t o = (size_t)row * C_DIM + h * HD + d;
            qhi[ks][r] = *(const uint32_t*)&g_qsh[o];
            qlo[ks][r] = *(const uint32_t*)&g_qsl[o];
        }
    }

    float oacc[16][4];
#pragma unroll
    for (int nf = 0; nf < 16; nf++)
#pragma unroll
        for (int e = 0; e < 4; e++) oacc[nf][e] = 0.0f;
    float m2[2]   = { -1e30f, -1e30f };
    float lsum[2] = { 0.0f, 0.0f };

    int jmin = qb * 64 - (WIN - 1);
    if (jmin < 0) jmin = 0;
    const int kb0 = jmin >> 5;
    const int kb1 = (qb * 64 + 63) >> 5;

    const int krow    = (lane & 7) + ((lane >> 4) << 3);
    const int kcoloff = ((lane >> 3) & 1) << 3;
    const int vrow    = (lane & 7) + (((lane >> 3) & 1) << 3);
    const int vcoloff = (lane >> 4) << 3;

    const uint32_t kh_ro = (uint32_t)(krow * KVS + kcoloff) * 2;
    const uint32_t vh_ro = (uint32_t)(vrow * KVS + vcoloff) * 2;
    const uint32_t KROW16 = (uint32_t)(16 * KVS) * 2;

    attn_load_kv(sbase, kb0 * 32, kvh, tid);
    cp_commit();

    int s = 0;
    for (int kb = kb0; kb <= kb1; kb++) {
        const int jb = kb * 32;
        if (kb < kb1) {
            attn_load_kv(sbase + (s ^ 1) * ATT_STAGE, (kb + 1) * 32, kvh, tid);
            cp_commit();
            cp_wait<1>();
        } else {
            cp_wait<0>();
        }
        __syncthreads();

        const uint32_t stb = sbase + s * ATT_STAGE;
        const uint32_t kh_base = stb + A_KH + kh_ro;
        const uint32_t kl_base = stb + A_KL + kh_ro;
        const uint32_t vh_base = stb + A_VH + vh_ro;
        const uint32_t vl_base = stb + A_VL + vh_ro;

        float sacc[4][4];
#pragma unroll
        for (int f = 0; f < 4; f++)
#pragma unroll
            for (int e = 0; e < 4; e++) sacc[f][e] = 0.0f;

#pragma unroll
        for (int ks = 0; ks < 8; ks++) {
            uint32_t off = (uint32_t)(ks * 16) * 2;
            uint32_t bh0[4], bh1[4], bl0[4], bl1[4];
            LDMATRIX_X4(bh0[0], bh0[1], bh0[2], bh0[3], kh_base + off);
            LDMATRIX_X4(bh1[0], bh1[1], bh1[2], bh1[3], kh_base + off + KROW16);
            LDMATRIX_X4(bl0[0], bl0[1], bl0[2], bl0[3], kl_base + off);
            LDMATRIX_X4(bl1[0], bl1[1], bl1[2], bl1[3], kl_base + off + KROW16);
            MMA_BF16(sacc[0], qhi[ks][0], qhi[ks][1], qhi[ks][2], qhi[ks][3], bh0[0], bh0[1]);
            MMA_BF16(sacc[1], qhi[ks][0], qhi[ks][1], qhi[ks][2], qhi[ks][3], bh0[2], bh0[3]);
            MMA_BF16(sacc[2], qhi[ks][0], qhi[ks][1], qhi[ks][2], qhi[ks][3], bh1[0], bh1[1]);
            MMA_BF16(sacc[3], qhi[ks][0], qhi[ks][1], qhi[ks][2], qhi[ks][3], bh1[2], bh1[3]);
            MMA_BF16(sacc[0], qlo[ks][0], qlo[ks][1], qlo[ks][2], qlo[ks][3], bh0[0], bh0[1]);
            MMA_BF16(sacc[1], qlo[ks][0], qlo[ks][1], qlo[ks][2], qlo[ks][3], bh0[2], bh0[3]);
            MMA_BF16(sacc[2], qlo[ks][0], qlo[ks][1], qlo[ks][2], qlo[ks][3], bh1[0], bh1[1]);
            MMA_BF16(sacc[3], qlo[ks][0], qlo[ks][1], qlo[ks][2], qlo[ks][3], bh1[2], bh1[3]);
            MMA_BF16(sacc[0], qhi[ks][0], qhi[ks][1], qhi[ks][2], qhi[ks][3], bl0[0], bl0[1]);
            MMA_BF16(sacc[1], qhi[ks][0], qhi[ks][1], qhi[ks][2], qhi[ks][3], bl0[2], bl0[3]);
            MMA_BF16(sacc[2], qhi[ks][0], qhi[ks][1], qhi[ks][2], qhi[ks][3], bl1[0], bl1[1]);
            MMA_BF16(sacc[3], qhi[ks][0], qhi[ks][1], qhi[ks][2], qhi[ks][3], bl1[2], bl1[3]);
        }

        float bm0 = -1e30f, bm1 = -1e30f;
#pragma unroll
        for (int f = 0; f < 4; f++) {
            int j0 = jb + f * 8 + tc2;
#pragma unroll
            for (int e = 0; e < 4; e++) {
                int j  = j0 + (e & 1);
                int qi = qrow0 + trow + ((e >> 1) << 3);
                bool ok = (j <= qi) && ((qi - j) < WIN);
                float sx = ok ? sacc[f][e] : -1e30f;
                sacc[f][e] = sx;
                if (e < 2) bm0 = fmaxf(bm0, sx); else bm1 = fmaxf(bm1, sx);
            }
        }
        bm0 = fmaxf(bm0, __shfl_xor_sync(0xffffffffu, bm0, 1));
        bm0 = fmaxf(bm0, __shfl_xor_sync(0xffffffffu, bm0, 2));
        bm1 = fmaxf(bm1, __shfl_xor_sync(0xffffffffu, bm1, 1));
        bm1 = fmaxf(bm1, __shfl_xor_sync(0xffffffffu, bm1, 2));

        float mn0 = fmaxf(m2[0], bm0);
        float mn1 = fmaxf(m2[1], bm1);
        float mm0 = fmaxf(mn0, -1e20f);
        float mm1 = fmaxf(mn1, -1e20f);
        float f0 = exp2f(m2[0] - mm0);
        float f1 = exp2f(m2[1] - mm1);
        m2[0] = mn0; m2[1] = mn1;

        float ps0 = 0.0f, ps1 = 0.0f;
#pragma unroll
        for (int f = 0; f < 4; f++) {
            sacc[f][0] = exp2f(sacc[f][0] - mm0);
            sacc[f][1] = exp2f(sacc[f][1] - mm0);
            sacc[f][2] = exp2f(sacc[f][2] - mm1);
            sacc[f][3] = exp2f(sacc[f][3] - mm1);
            ps0 += sacc[f][0] + sacc[f][1];
            ps1 += sacc[f][2] + sacc[f][3];
        }
        ps0 += __shfl_xor_sync(0xffffffffu, ps0, 1);
        ps0 += __shfl_xor_sync(0xffffffffu, ps0, 2);
        ps1 += __shfl_xor_sync(0xffffffffu, ps1, 1);
        ps1 += __shfl_xor_sync(0xffffffffu, ps1, 2);
        lsum[0] = lsum[0] * f0 + ps0;
        lsum[1] = lsum[1] * f1 + ps1;

#pragma unroll
        for (int nf = 0; nf < 16; nf++) {
            oacc[nf][0] *= f0; oacc[nf][1] *= f0;
            oacc[nf][2] *= f1; oacc[nf][3] *= f1;
        }

        uint32_t phi[2][4], plo[2][4];
#pragma unroll
        for (int kp = 0; kp < 2; kp++) {
            split2(sacc[2*kp][0],   sacc[2*kp][1],   phi[kp][0], plo[kp][0]);
            split2(sacc[2*kp][2],   sacc[2*kp][3],   phi[kp][1], plo[kp][1]);
            split2(sacc[2*kp+1][0], sacc[2*kp+1][1], phi[kp][2], plo[kp][2]);
            split2(sacc[2*kp+1][2], sacc[2*kp+1][3], phi[kp][3], plo[kp][3]);
        }

#pragma unroll
        for (int kp = 0; kp < 2; kp++) {
            uint32_t rowoff = (uint32_t)(kp * 16 * KVS) * 2;
#pragma unroll
            for (int ng = 0; ng < 8; ng++) {
                uint32_t coff = rowoff + (uint32_t)(ng * 16) * 2;
                uint32_t vh4[4], vl4[4];
                LDMATRIX_X4_T(vh4[0], vh4[1], vh4[2], vh4[3], vh_base + coff);
                LDMATRIX_X4_T(vl4[0], vl4[1], vl4[2], vl4[3], vl_base + coff);
                MMA_BF16(oacc[2*ng],   phi[kp][0], phi[kp][1], phi[kp][2], phi[kp][3], vh4[0], vh4[1]);
                MMA_BF16(oacc[2*ng+1], phi[kp][0], phi[kp][1], phi[kp][2], phi[kp][3], vh4[2], vh4[3]);
                MMA_BF16(oacc[2*ng],   plo[kp][0], plo[kp][1], plo[kp][2], plo[kp][3], vh4[0], vh4[1]);
                MMA_BF16(oacc[2*ng+1], plo[kp][0], plo[kp][1], plo[kp][2], plo[kp][3], vh4[2], vh4[3]);
                MMA_BF16(oacc[2*ng],   phi[kp][0], phi[kp][1], phi[kp][2], phi[kp][3], vl4[0], vl4[1]);
                MMA_BF16(oacc[2*ng+1], phi[kp][0], phi[kp][1], phi[kp][2], phi[kp][3], vl4[2], vl4[3]);
            }
        }
        __syncthreads();
        s ^= 1;
    }

    float il0 = 1.0f / lsum[0];
    float il1 = 1.0f / lsum[1];
    const int row0 = qrow0 + trow;
#pragma unroll
    for (int nf = 0; nf < 16; nf++) {
        int col = h * HD + nf * 8 + tc2;
        uint32_t hh, ll;
        split2(oacc[nf][0] * il0, oacc[nf][1] * il0, hh, ll);
        *(uint32_t*)&Yh[(size_t)row0 * C_DIM + col] = hh;
        *(uint32_t*)&Yl[(size_t)row0 * C_DIM + col] = ll;
        split2(oacc[nf][2] * il1, oacc[nf][3] * il1, hh, ll);
        *(uint32_t*)&Yh[(size_t)(row0 + 8) * C_DIM + col] = hh;
        *(uint32_t*)&Yl[(size_t)(row0 + 8) * C_DIM + col] = ll;
    }
}

// ---------------------------------------------------------------------------
// Launch (position #4 = Wq GEMM for ncu capture)
// ---------------------------------------------------------------------------
extern "C" void kernel_launch(void* const* d_in, const int* in_sizes, int n_in,
                              void* d_out, int out_size)
{
    const float* x  = (const float*)d_in[0];
    const float* Wq = (const float*)d_in[1];
    const float* Wk = (const float*)d_in[2];
    const float* Wv = (const float*)d_in[3];
    const float* Wo = (const float*)d_in[4];
    float* out = (float*)d_out;

    float *Q, *Kp;
    cudaGetSymbolAddress((void**)&Q,  g_Q);
    cudaGetSymbolAddress((void**)&Kp, g_K);

    __nv_bfloat16 *xh, *xl, *yh, *yl, *wqh, *wql, *woh, *wol;
    cudaGetSymbolAddress((void**)&xh, g_xh);
    cudaGetSymbolAddress((void**)&xl, g_xl);
    cudaGetSymbolAddress((void**)&yh, g_yh);
    cudaGetSymbolAddress((void**)&yl, g_yl);
    cudaGetSymbolAddress((void**)&wqh, g_wqt_h);
    cudaGetSymbolAddress((void**)&wql, g_wqt_l);
    cudaGetSymbolAddress((void**)&woh, g_wot_h);
    cudaGetSymbolAddress((void**)&wol, g_wot_l);

    static bool attr_done = false;
    if (!attr_done) {
        cudaFuncSetAttribute(gemm_one, cudaFuncAttributeMaxDynamicSharedMemorySize, G2_SMEM);
        cudaFuncSetAttribute(gemm_kv,  cudaFuncAttributeMaxDynamicSharedMemorySize, G2_SMEM);
        cudaFuncSetAttribute(attn_tc_kernel, cudaFuncAttributeMaxDynamicSharedMemorySize, ATT_SMEM);
        attr_done = true;
    }

    // 1: RoPE table
    rope_table_kernel<<<(T_LEN * 64) / 256, 256>>>();
    // 2: split x
    split_f32_kernel<<<(T_LEN * C_DIM / 4 + 255) / 256, 256>>>(x, xh, xl, T_LEN * C_DIM / 4);
    // 3: transpose Wq + Wo
    transpose_qo_kernel<<<dim3(C_DIM / 32, C_DIM / 32, 2), dim3(32, 8)>>>(Wq, Wo);
    // 4: Q projection  <-- profiled launch
    gemm_one<<<dim3((HQ * HD) / 128, T_LEN / 256), 256, G2_SMEM>>>(xh, xl, wqh, wql, Q, T_LEN, HQ * HD, C_DIM);
    // 5: transpose Wk + Wv
    transpose_kv_kernel<<<dim3(NKV / 32, C_DIM / 32, 2), dim3(32, 8)>>>(Wk, Wv);
    // 6: K + V projections
    gemm_kv<<<dim3(NKV / 128, T_LEN / 256, 2), 256, G2_SMEM>>>(xh, xl, Kp);
    // 7: RoPE apply + split
    const int n_rope2 = T_LEN * HQ * 32 + T_LEN * HKV * 32;
    rope_apply_split_kernel<<<n_rope2 / 256, 256>>>(Q, Kp);
    // 8: attention
    attn_tc_kernel<<<dim3(T_LEN / 64, HQ), 128, ATT_SMEM>>>(yh, yl);
    // 9: output projection
    gemm_one<<<dim3(C_DIM / 128, T_LEN / 256), 256, G2_SMEM>>>(yh, yl, woh, wol, out, T_LEN, C_DIM, C_DIM);
}